// round 13
// baseline (speedup 1.0000x reference)
#include <cuda_runtime.h>
#include <cuda_fp16.h>

#define HH 2048
#define WW 2048
#define TX 32
#define TYO 32                    // output rows per block (2 per thread)
#define NTHREADS 512
#define HTX 34
#define HTY 34
#define HALO_PIX (HTX * HTY)      // 1156
#define HPITCH ((HALO_PIX + 1) * 16)  // +1 pad pixel: dot pass reads up to pixel 1156
#define DOT_ROWS (TYO + 1)        // 33
#define DOT_POS (DOT_ROWS * HTX)  // 1122

__device__ __forceinline__ float dot4(float4 a, float4 b) {
    return a.x * b.x + a.y * b.y + a.z * b.z + a.w * b.w;
}

__device__ __forceinline__ unsigned h2u(half2 h) {
    return *(const unsigned*)&h;
}

// 8-channel packet dot: fp16 mul/acc (4-deep chain), f32 finish.
__device__ __forceinline__ float dot_pkt(uint4 a, uint4 b) {
    const half2* ha = (const half2*)&a;
    const half2* hb = (const half2*)&b;
    half2 acc = __hmul2(ha[0], hb[0]);
    acc = __hfma2(ha[1], hb[1], acc);
    acc = __hfma2(ha[2], hb[2], acc);
    acc = __hfma2(ha[3], hb[3], acc);
    float2 f = __half22float2(acc);
    return f.x + f.y;
}

// Normalize one float4 chunk (4 lanes of a pixel share the norm via shfl),
// store as fp16 at precomputed byte offset. All 32 lanes must participate.
__device__ __forceinline__ void norm_store(unsigned char* sH, float4 v,
                                           unsigned off, bool write) {
    float s = dot4(v, v);
    s += __shfl_xor_sync(0xffffffffu, s, 1);
    s += __shfl_xor_sync(0xffffffffu, s, 2);
    float r = rsqrtf(fmaxf(s, 1e-24f));
    if (write) {
        half2 ha = __floats2half2_rn(v.x * r, v.y * r);
        half2 hb = __floats2half2_rn(v.z * r, v.w * r);
        *(uint2*)(sH + off) = make_uint2(h2u(ha), h2u(hb));
    }
}

__global__ __launch_bounds__(NTHREADS, 4)
void cos_sim_kernel(const float* __restrict__ img, float* __restrict__ out) {
    __shared__ __align__(16) unsigned char sH[2 * HPITCH];
    __shared__ float sD1[DOT_POS];   // dot(p, p + (1,+1))
    __shared__ float sD2[DOT_POS];   // dot(p, p + (1,-1))

    const int tx = threadIdx.x;
    const int ty = threadIdx.y;      // 0..15
    const int bx = blockIdx.x * TX;
    const int by = blockIdx.y * TYO;
    const int tid = ty * TX + tx;

    const float4* __restrict__ img4 = (const float4*)img;

    // ---- Stage body: halo rows 0..33, cols 1..32 (pixel cols bx..bx+31). ----
    // Per-thread role fixed: ch = tid&3, col = (tid>>2)&31, row0 = tid>>7 (0..3).
    // Each iteration advances row by 4 -> constant address deltas:
    //   4 rows * WW pixels * 4 float4/pixel = 16*WW float4 elements.
    {
        const int ch   = tid & 3;
        const int col  = (tid >> 2) & 31;
        const int row0 = tid >> 7;
        const int gy0  = by - 1 + row0;
        const float4* gp = img4 + ((long long)gy0 * WW + (bx + col)) * 4 + ch;
        const unsigned soff0 = (unsigned)(ch >> 1) * HPITCH
                             + (unsigned)(row0 * HTX + col + 1) * 16u
                             + (unsigned)(ch & 1) * 8u;

        #pragma unroll
        for (int it = 0; it < 9; it++) {
            bool act = (it < 8) | (tid < 256);       // 4352 f4 = 8.5 * 512
            int gy = gy0 + 4 * it;
            float4 v = make_float4(0.f, 0.f, 0.f, 0.f);
            if (act && (unsigned)gy < HH)
                v = gp[(size_t)it * 16 * WW];        // 4 halo rows per step
            norm_store(sH, v, soff0 + (unsigned)it * (4 * HTX * 16), act);
        }
    }

    // ---- Stage edges: halo cols 0 and 33, rows 0..33. ----
    {
        int side = tid >> 8;                 // 0 -> col 0, 1 -> col 33
        int row  = (tid >> 2) & 63;
        int ch   = tid & 3;
        bool act = row < HTY;
        int gy = by - 1 + row;
        int gx = bx - 1 + side * 33;
        float4 v = make_float4(0.f, 0.f, 0.f, 0.f);
        if (act && (unsigned)gy < HH && (unsigned)gx < WW)
            v = img4[((long long)gy * WW + gx) * 4 + ch];
        unsigned off = (unsigned)(ch >> 1) * HPITCH
                     + (unsigned)(row * HTX + side * 33) * 16u
                     + (unsigned)(ch & 1) * 8u;
        norm_store(sH, v, off, act);
    }
    __syncthreads();

    // ---- Dot pass: each diagonal pair dot ONCE; plane-at-a-time to keep
    //      live registers low (target 32 regs -> 4 blocks/SM). ----
    #pragma unroll
    for (int it = 0; it < 3; it++) {
        int p = tid + it * NTHREADS;
        if (p < DOT_POS) {
            const unsigned a = (unsigned)p * 16u;
            float d1, d2;
            {
                uint4 ub = *(const uint4*)(sH + a);
                uint4 ur = *(const uint4*)(sH + a + (HTX + 1) * 16);
                uint4 ul = *(const uint4*)(sH + a + (HTX - 1) * 16);
                d1 = dot_pkt(ub, ur);
                d2 = dot_pkt(ub, ul);
            }
            {
                uint4 ub = *(const uint4*)(sH + HPITCH + a);
                uint4 ur = *(const uint4*)(sH + HPITCH + a + (HTX + 1) * 16);
                uint4 ul = *(const uint4*)(sH + HPITCH + a + (HTX - 1) * 16);
                d1 += dot_pkt(ub, ur);
                d2 += dot_pkt(ub, ul);
            }
            sD1[p] = d1;
            sD2[p] = d2;
        }
    }
    __syncthreads();

    // ---- Gather: 2 outputs per thread, 4 shared pair-dots each. ----
    #pragma unroll
    for (int half = 0; half < 2; half++) {
        int oy = ty + half * 16;
        int pc = (oy + 1) * HTX + (tx + 1);
        float sim = (sD1[pc] + sD1[pc - HTX - 1])
                  + (sD2[pc] + sD2[pc - HTX + 1]);
        out[(size_t)(by + oy) * WW + (bx + tx)] = sim;
    }
}

extern "C" void kernel_launch(void* const* d_in, const int* in_sizes, int n_in,
                              void* d_out, int out_size) {
    const float* img = (const float*)d_in[0];
    float* out = (float*)d_out;

    dim3 block(TX, 16);
    dim3 grid(WW / TX, HH / TYO);   // 64 x 64
    cos_sim_kernel<<<grid, block>>>(img, out);
}

// round 15
// speedup vs baseline: 1.1079x; 1.1079x over previous
#include <cuda_runtime.h>
#include <cuda_fp16.h>

#define HH 2048
#define WW 2048
#define OUTCOLS 30                  // output columns per warp (lanes 1..30)
#define NSTRIPS 69                  // ceil(2048 / 30)
#define SEGROWS 32                  // output rows per warp segment
#define NSEGY (HH / SEGROWS)        // 64
#define NWARPS (NSTRIPS * NSEGY)    // 4416
#define TPB 256
#define NBLOCKS (NWARPS / (TPB / 32))  // 552

struct HVec { half2 h[8]; };        // one pixel, 16 channels normalized fp16

__device__ __forceinline__ float dot4(float4 a, float4 b) {
    return a.x * b.x + a.y * b.y + a.z * b.z + a.w * b.w;
}

// Two 4-deep fp16 chains + f32 combine (same numerics as prior rounds).
__device__ __forceinline__ float hdot(const HVec& a, const HVec& b) {
    half2 c0 = __hmul2(a.h[0], b.h[0]);
    c0 = __hfma2(a.h[1], b.h[1], c0);
    c0 = __hfma2(a.h[2], b.h[2], c0);
    c0 = __hfma2(a.h[3], b.h[3], c0);
    half2 c1 = __hmul2(a.h[4], b.h[4]);
    c1 = __hfma2(a.h[5], b.h[5], c1);
    c1 = __hfma2(a.h[6], b.h[6], c1);
    c1 = __hfma2(a.h[7], b.h[7], c1);
    float2 f0 = __half22float2(c0);
    float2 f1 = __half22float2(c1);
    return (f0.x + f0.y) + (f1.x + f1.y);
}

// Get lane c+1's vector (lane 31 result unused by construction).
__device__ __forceinline__ HVec shfl_down_vec(const HVec& a) {
    HVec r;
    #pragma unroll
    for (int j = 0; j < 8; j++) {
        unsigned u = __shfl_down_sync(0xffffffffu, *(const unsigned*)&a.h[j], 1);
        r.h[j] = *(const half2*)&u;
    }
    return r;
}

__device__ __forceinline__ void load_raw(const float4* __restrict__ img4,
                                         int y, int colc, bool ok, float4 v[4]) {
    v[0] = v[1] = v[2] = v[3] = make_float4(0.f, 0.f, 0.f, 0.f);
    if (ok && (unsigned)y < HH) {
        const float4* p = img4 + 4ll * ((long long)y * WW + colc);
        v[0] = p[0]; v[1] = p[1]; v[2] = p[2]; v[3] = p[3];
    }
}

__device__ __forceinline__ HVec norm_pack(const float4 v[4]) {
    float s = dot4(v[0], v[0]) + dot4(v[1], v[1])
            + dot4(v[2], v[2]) + dot4(v[3], v[3]);
    float r = rsqrtf(fmaxf(s, 1e-24f));   // zero (halo/OOB) stays exactly zero
    HVec o;
    #pragma unroll
    for (int k = 0; k < 4; k++) {
        o.h[2 * k]     = __floats2half2_rn(v[k].x * r, v[k].y * r);
        o.h[2 * k + 1] = __floats2half2_rn(v[k].z * r, v[k].w * r);
    }
    return o;
}

__global__ __launch_bounds__(TPB)
void cos_sim_kernel(const float* __restrict__ img, float* __restrict__ out) {
    const float4* __restrict__ img4 = (const float4*)img;

    const int lane  = threadIdx.x & 31;
    const int gw    = blockIdx.x * (TPB / 32) + (threadIdx.x >> 5);
    const int strip = gw >> 6;           // / NSEGY
    const int segy  = gw & (NSEGY - 1);
    const int col   = strip * OUTCOLS - 1 + lane;
    const bool colv = (unsigned)col < WW;
    const bool writer = (lane >= 1) && (lane <= OUTCOLS) && colv;
    const int colc  = min(max(col, 0), WW - 1);   // clamped addr; predicate guards
    const int rtop  = segy * SEGROWS;

    // Prime: prev = row rtop-1, cur = row rtop (both zero-padded at image edge).
    float4 raw[4];
    load_raw(img4, rtop - 1, colc, colv, raw);
    HVec prev = norm_pack(raw);
    load_raw(img4, rtop, colc, colv, raw);
    HVec cur = norm_pack(raw);

    float up_acc = 0.0f;                     // up-pair contribution for row y
    float* op = out + (size_t)rtop * WW + col;

    // Pair k processes rows (rtop+k-1, rtop+k); 33 pairs finalize 32 outputs.
    #pragma unroll 2
    for (int k = 0; k <= SEGROWS; k++) {
        const int y = rtop + k;
        // Prefetch next row's raw data (rows rtop+1 .. rtop+SEGROWS).
        load_raw(img4, y + 1, colc, colv && (k < SEGROWS), raw);

        HVec curp  = shfl_down_vec(cur);     // cur[c+1]
        HVec prevp = shfl_down_vec(prev);    // prev[c+1]
        float A = hdot(prev, curp);          // dot(prev[c],  cur[c+1])
        float Z = hdot(prevp, cur);          // dot(prev[c+1], cur[c])
        float B  = __shfl_up_sync(0xffffffffu, Z, 1);  // dot(prev[c], cur[c-1])
        float Au = __shfl_up_sync(0xffffffffu, A, 1);  // dot(prev[c-1], cur[c])

        if (k > 0) {                          // finalize out(y-1, col)
            if (writer) *op = up_acc + A + B;
            op += WW;
        }
        up_acc = Au + Z;                      // up-pair sum for row y
        prev = cur;
        cur = norm_pack(raw);
    }
}

extern "C" void kernel_launch(void* const* d_in, const int* in_sizes, int n_in,
                              void* d_out, int out_size) {
    const float* img = (const float*)d_in[0];
    float* out = (float*)d_out;
    cos_sim_kernel<<<NBLOCKS, TPB>>>(img, out);
}

// round 16
// speedup vs baseline: 1.1433x; 1.0320x over previous
#include <cuda_runtime.h>
#include <cuda_fp16.h>

#define HH 2048
#define WW 2048
#define OUTCOLS 30                  // output columns per warp (lanes 1..30)
#define NSTRIPS 69                  // ceil(2048 / 30)
#define SEGROWS 16                  // output rows per warp segment
#define NSEGY (HH / SEGROWS)        // 128
#define NWARPS (NSTRIPS * NSEGY)    // 8832
#define TPB 256
#define WPB (TPB / 32)
#define NBLOCKS (NWARPS / WPB)      // 1104

struct HV { uint4 a, b; };          // one pixel: 16 ch normalized fp16 (8 half2)

__device__ __forceinline__ float dot4(float4 a, float4 b) {
    return a.x * b.x + a.y * b.y + a.z * b.z + a.w * b.w;
}

__device__ __forceinline__ unsigned h2u(half2 h) {
    return *(const unsigned*)&h;
}

// Two 4-deep fp16 chains + f32 combine (same numerics as prior rounds).
__device__ __forceinline__ float hdot(const HV& x, const HV& y) {
    const half2* hx = (const half2*)&x;
    const half2* hy = (const half2*)&y;
    half2 c0 = __hmul2(hx[0], hy[0]);
    c0 = __hfma2(hx[1], hy[1], c0);
    c0 = __hfma2(hx[2], hy[2], c0);
    c0 = __hfma2(hx[3], hy[3], c0);
    half2 c1 = __hmul2(hx[4], hy[4]);
    c1 = __hfma2(hx[5], hy[5], c1);
    c1 = __hfma2(hx[6], hy[6], c1);
    c1 = __hfma2(hx[7], hy[7], c1);
    float2 f0 = __half22float2(c0);
    float2 f1 = __half22float2(c1);
    return (f0.x + f0.y) + (f1.x + f1.y);
}

__device__ __forceinline__ HV shfl_down_hv(const HV& v) {
    HV r;
    const unsigned* s = (const unsigned*)&v;
    unsigned* d = (unsigned*)&r;
    #pragma unroll
    for (int j = 0; j < 8; j++)
        d[j] = __shfl_down_sync(0xffffffffu, s[j], 1);
    return r;
}

// Coalesced-loaded row (lane holds chunk lane&3 of pixel 8j+(lane>>2) in rw[j])
// -> 4-lane partial-norm reduce -> fp16 pack -> smem transpose -> lane owns
// its whole pixel (pixel index == lane). All 32 lanes participate.
__device__ __forceinline__ HV xpose_norm(const float4 rw[4],
                                         unsigned char* sb, int lane) {
    #pragma unroll
    for (int j = 0; j < 4; j++) {
        float s = dot4(rw[j], rw[j]);
        s += __shfl_xor_sync(0xffffffffu, s, 1);
        s += __shfl_xor_sync(0xffffffffu, s, 2);
        float inv = rsqrtf(fmaxf(s, 1e-24f));   // all-zero pixel stays zero
        half2 h0 = __floats2half2_rn(rw[j].x * inv, rw[j].y * inv);
        half2 h1 = __floats2half2_rn(rw[j].z * inv, rw[j].w * inv);
        *(uint2*)(sb + (32u * j + (unsigned)lane) * 8u) =
            make_uint2(h2u(h0), h2u(h1));
    }
    __syncwarp();
    HV o;
    o.a = *(const uint4*)(sb + (unsigned)lane * 32u);
    o.b = *(const uint4*)(sb + (unsigned)lane * 32u + 16u);
    return o;
}

__global__ __launch_bounds__(TPB, 4)
void cos_sim_kernel(const float* __restrict__ img, float* __restrict__ out) {
    __shared__ __align__(16) unsigned char sbuf[WPB][2][1024];

    const int lane = threadIdx.x & 31;
    const int wib  = threadIdx.x >> 5;
    const int gw   = blockIdx.x * WPB + wib;
    const int strip = gw >> 7;               // / NSEGY (128)
    const int segy  = gw & (NSEGY - 1);
    const int pix0  = strip * OUTCOLS - 1;   // pixel column of lane 0
    const int col   = pix0 + lane;
    const bool writer = (lane >= 1) && (lane <= OUTCOLS) && (col < WW);
    const int rtop  = segy * SEGROWS;

    // Per-lane coalesced-load geometry (4 batches of 32 float4 per row).
    int  off[4];
    bool val[4];
    #pragma unroll
    for (int j = 0; j < 4; j++) {
        int p = pix0 + 8 * j + (lane >> 2);
        val[j] = (unsigned)p < WW;
        int pc = min(max(p, 0), WW - 1);
        off[j] = pc * 4 + (lane & 3);
    }

    const float4* __restrict__ img4 = (const float4*)img;
    unsigned char* b0 = sbuf[wib][0];
    unsigned char* b1 = sbuf[wib][1];

    float4 rw[4];
    auto loadrow = [&](int y, bool en) {
        bool rok = en && ((unsigned)y < HH);
        const float4* rp = img4 + (long long)min(max(y, 0), HH - 1) * (WW * 4);
        #pragma unroll
        for (int j = 0; j < 4; j++) {
            float4 v = make_float4(0.f, 0.f, 0.f, 0.f);
            if (rok && val[j]) v = rp[off[j]];
            rw[j] = v;
        }
    };

    // Prime: prev = row rtop-1 (buf0), cur = row rtop (buf1).
    loadrow(rtop - 1, true);
    HV prev = xpose_norm(rw, b0, lane);
    loadrow(rtop, true);
    HV cur = xpose_norm(rw, b1, lane);
    HV prevp = shfl_down_hv(prev);           // prev[c+1]

    float up_acc = 0.0f;
    float* op = out + (size_t)rtop * WW + col;

    // Pair k handles rows (rtop+k-1, rtop+k); 17 pairs finalize 16 outputs.
    #pragma unroll 1
    for (int k = 0; k <= SEGROWS; k++) {
        loadrow(rtop + k + 1, k < SEGROWS);  // prefetch next row

        HV curp = shfl_down_hv(cur);         // cur[c+1]
        float A = hdot(prev, curp);          // dot(prev[c],   cur[c+1])
        float Z = hdot(prevp, cur);          // dot(prev[c+1], cur[c])
        float B  = __shfl_up_sync(0xffffffffu, Z, 1);  // dot(prev[c-1+1?]... = Z[c-1]
        float Au = __shfl_up_sync(0xffffffffu, A, 1);  // A[c-1]

        if (k > 0) {                         // finalize out(rtop+k-1, col)
            if (writer) *op = up_acc + A + B;
            op += WW;
        }
        up_acc = Au + Z;                     // up-pair sum for next output row
        prev = cur;
        prevp = curp;                        // shfl_down(prev) reused, no recompute
        if (k < SEGROWS)
            cur = xpose_norm(rw, (k & 1) ? b1 : b0, lane);
    }
}

extern "C" void kernel_launch(void* const* d_in, const int* in_sizes, int n_in,
                              void* d_out, int out_size) {
    const float* img = (const float*)d_in[0];
    float* out = (float*)d_out;
    cos_sim_kernel<<<NBLOCKS, TPB>>>(img, out);
}